// round 16
// baseline (speedup 1.0000x reference)
#include <cuda_runtime.h>
#include <cuda_fp16.h>
#include <math.h>
#include <stdint.h>

#define N_NODES 100000
#define N_EDGES 1600000
#define IN_F 64
#define HID_F 64
#define OUT_F 16

#define SCAN_B 1024
#define MAX_SCAN_BLKS 128

// ---- scratch (static __device__ globals) ----
__device__ __align__(16) int    g_cnt[N_NODES];     // in-degree (zeroed by last kernel)
__device__ __align__(16) int    g_row[N_NODES];     // CSR exclusive offsets (begin)
__device__ __align__(16) int    g_rank[N_EDGES];    // edge rank within dst bucket
__device__ __align__(16) int    g_blksum[MAX_SCAN_BLKS];
__device__ __align__(16) float  g_dis[N_NODES];     // rsqrt(deg+1)
__device__ __align__(16) int    g_csr[N_EDGES];     // src << 7 (byte offset of h1 row)
__device__ __align__(16) __half g_h1[(size_t)N_NODES * HID_F];  // x@W1; scaled in place
__device__ __align__(16) float  g_agg1[(size_t)N_NODES * HID_F];
__device__ __align__(16) __half g_h2[(size_t)N_NODES * OUT_F];  // dis[n]*h2, fp16

// packed f32x2 helpers (sm_103a)
#define PACK2(out, lo, hi) \
    asm("mov.b64 %0, {%1, %2};" : "=l"(out) : "f"(lo), "f"(hi))
#define UNPACK2(lo, hi, in) \
    asm("mov.b64 {%0, %1}, %2;" : "=f"(lo), "=f"(hi) : "l"(in))
#define FMA2(acc, a, b) \
    asm("fma.rn.f32x2 %0, %1, %2, %0;" : "+l"(acc) : "l"(a), "l"(b))

// inline dtype detect: int64 node ids < 2^31 have zero odd 32-bit words
__device__ __forceinline__ int edge_stride(const int* __restrict__ ei32, int E) {
    int is64 = 1;
    int n = E < 16 ? E : 16;
#pragma unroll
    for (int i = 0; i < 16; i++)
        if (i < n && ei32[2 * i + 1] != 0) is64 = 0;
    return is64 ? 2 : 1;
}

// ---------------------------------------------------------------------------
// degree histogram on dst; stores per-edge rank within its bucket
__global__ void build_hist_kernel(const int* __restrict__ ei32, int E) {
    int e = blockIdx.x * blockDim.x + threadIdx.x;
    if (e >= E) return;
    int stride = edge_stride(ei32, E);
    int dst = ei32[((size_t)E + e) * stride];
    g_rank[e] = atomicAdd(&g_cnt[dst], 1);
}

// per-block exclusive scan (warp-shuffle, 2 barriers)
__global__ __launch_bounds__(SCAN_B) void scan1_kernel(int N) {
    __shared__ int wsum[32];
    int i = blockIdx.x * SCAN_B + threadIdx.x;
    int v = (i < N) ? g_cnt[i] : 0;
    int lane = threadIdx.x & 31, wid = threadIdx.x >> 5;

    int s = v;
#pragma unroll
    for (int o = 1; o < 32; o *= 2) {
        int t = __shfl_up_sync(0xffffffffu, s, o);
        if (lane >= o) s += t;
    }
    if (lane == 31) wsum[wid] = s;
    __syncthreads();
    if (wid == 0) {
        int w = wsum[lane];
        int ws = w;
#pragma unroll
        for (int o = 1; o < 32; o *= 2) {
            int t = __shfl_up_sync(0xffffffffu, ws, o);
            if (lane >= o) ws += t;
        }
        wsum[lane] = ws - w;
        if (lane == 31) g_blksum[blockIdx.x] = ws;
    }
    __syncthreads();
    if (i < N) g_row[i] = wsum[wid] + s - v;       // exclusive
}

// fixup: warp 0 scans block sums (4/lane); final offsets + dis
__global__ void scan3_kernel(int N, int nblks) {
    __shared__ int excl[MAX_SCAN_BLKS];
    int lane = threadIdx.x & 31;
    if (threadIdx.x < 32) {
        int b4 = lane * 4;
        int v0 = (b4 + 0 < nblks) ? g_blksum[b4 + 0] : 0;
        int v1 = (b4 + 1 < nblks) ? g_blksum[b4 + 1] : 0;
        int v2 = (b4 + 2 < nblks) ? g_blksum[b4 + 2] : 0;
        int v3 = (b4 + 3 < nblks) ? g_blksum[b4 + 3] : 0;
        int s4 = v0 + v1 + v2 + v3;
        int ss = s4;
#pragma unroll
        for (int o = 1; o < 32; o *= 2) {
            int t = __shfl_up_sync(0xffffffffu, ss, o);
            if (lane >= o) ss += t;
        }
        int ex = ss - s4;
        excl[b4 + 0] = ex;
        excl[b4 + 1] = ex + v0;
        excl[b4 + 2] = ex + v0 + v1;
        excl[b4 + 3] = ex + v0 + v1 + v2;
    }
    __syncthreads();
    int i = blockIdx.x * blockDim.x + threadIdx.x;
    if (i >= N) return;
    g_row[i] += excl[i >> 10];
    g_dis[i] = rsqrtf((float)(g_cnt[i] + 1));
}

// bucket fill — atomic-free; stores BYTE OFFSET of src's h1 row (src<<7)
__global__ void fill_kernel(const int* __restrict__ ei32, int E) {
    int e = blockIdx.x * blockDim.x + threadIdx.x;
    if (e >= E) return;
    int stride = edge_stride(ei32, E);
    int src = ei32[(size_t)e * stride];
    int dst = ei32[((size_t)E + e) * stride];
    g_csr[g_row[dst] + g_rank[e]] = src << 7;
}

// ---------------------------------------------------------------------------
// GEMM1: h1 = x @ W1 (RAW). Block tile 128x64, thread tile 4x8, 256 threads.
// Inner product via packed fma.rn.f32x2 (2 FMA per instruction, exact fp32).
__global__ __launch_bounds__(256) void gemm1_kernel(
    const float* __restrict__ x, const float* __restrict__ W1, int N) {
    __shared__ float Wsh[IN_F][HID_F];   // 16KB
    __shared__ float Xsh[16][128];       // 8KB per k-chunk (transposed)

    int tid = threadIdx.x;
    int tx = tid & 7;          // out group: outs tx*8..tx*8+7
    int ty = tid >> 3;         // node group: nodes ty*4..ty*4+3
    int nb = blockIdx.x * 128;

    for (int i = tid; i < 1024; i += 256) {
        int row = i >> 4, c4 = (i & 15) << 2;
        *reinterpret_cast<float4*>(&Wsh[row][c4]) =
            *reinterpret_cast<const float4*>(&W1[row * HID_F + c4]);
    }

    // acc2[i][p] = packed (out[2p], out[2p+1]) for node i
    unsigned long long acc2[4][4];
#pragma unroll
    for (int i = 0; i < 4; i++)
#pragma unroll
        for (int p = 0; p < 4; p++) acc2[i][p] = 0ull;

    for (int kc = 0; kc < 4; kc++) {
        int k0 = kc * 16;
        __syncthreads();
        for (int i = tid; i < 512; i += 256) {
            int node = i >> 2, k4 = (i & 3) << 2;
            float4 v = make_float4(0.f, 0.f, 0.f, 0.f);
            int n = nb + node;
            if (n < N)
                v = *reinterpret_cast<const float4*>(&x[(size_t)n * IN_F + k0 + k4]);
            Xsh[k4 + 0][node] = v.x;
            Xsh[k4 + 1][node] = v.y;
            Xsh[k4 + 2][node] = v.z;
            Xsh[k4 + 3][node] = v.w;
        }
        __syncthreads();
#pragma unroll
        for (int k = 0; k < 16; k++) {
            float4 xv = *reinterpret_cast<const float4*>(&Xsh[k][ty * 4]);
            float4 wa = *reinterpret_cast<const float4*>(&Wsh[k0 + k][tx * 8]);
            float4 wb = *reinterpret_cast<const float4*>(&Wsh[k0 + k][tx * 8 + 4]);
            unsigned long long w01, w23, w45, w67;
            PACK2(w01, wa.x, wa.y);
            PACK2(w23, wa.z, wa.w);
            PACK2(w45, wb.x, wb.y);
            PACK2(w67, wb.z, wb.w);
            float xs[4] = {xv.x, xv.y, xv.z, xv.w};
#pragma unroll
            for (int i = 0; i < 4; i++) {
                unsigned long long xd;
                PACK2(xd, xs[i], xs[i]);
                FMA2(acc2[i][0], xd, w01);
                FMA2(acc2[i][1], xd, w23);
                FMA2(acc2[i][2], xd, w45);
                FMA2(acc2[i][3], xd, w67);
            }
        }
    }

#pragma unroll
    for (int i = 0; i < 4; i++) {
        int n = nb + ty * 4 + i;
        if (n >= N) continue;
        __align__(16) __half2 h[4];
#pragma unroll
        for (int p = 0; p < 4; p++) {
            float lo, hi;
            UNPACK2(lo, hi, acc2[i][p]);
            h[p] = __floats2half2_rn(lo, hi);
        }
        *reinterpret_cast<uint4*>(&g_h1[(size_t)n * HID_F + tx * 8]) =
            *reinterpret_cast<uint4*>(h);
    }
}

// scale h1 in place by dis[n]. 8 threads/node, 16B each. Hidden under fill.
__global__ __launch_bounds__(256) void scale_h1_kernel(int N) {
    int t = blockIdx.x * blockDim.x + threadIdx.x;
    int n = t >> 3;
    int c = t & 7;
    if (n >= N) return;
    float dn = g_dis[n];
    uint4 raw = *reinterpret_cast<const uint4*>(&g_h1[(size_t)n * HID_F + c * 8]);
    __half2* hp = reinterpret_cast<__half2*>(&raw);
#pragma unroll
    for (int p = 0; p < 4; p++) {
        float2 f = __half22float2(hp[p]);
        hp[p] = __floats2half2_rn(f.x * dn, f.y * dn);
    }
    *reinterpret_cast<uint4*>(&g_h1[(size_t)n * HID_F + c * 8]) = raw;
}

// ---------------------------------------------------------------------------
// gather layer 1 — warp per node, offset csr, 8 edges/iter, 1 HADD2 level:
//   agg1[n] = dis[n] * ( h1s[n] + sum_s h1s[s] )
__global__ __launch_bounds__(256) void gather1_kernel(int N) {
    int n = (blockIdx.x * blockDim.x + threadIdx.x) >> 5;
    unsigned lane = threadIdx.x & 31;
    if (n >= N) return;

    const char* h1b = reinterpret_cast<const char*>(g_h1);
    unsigned lo = lane * 4u;

    float dn = g_dis[n];
    int beg = g_row[n];
    int end = beg + g_cnt[n];

    float2 acc = __half22float2(
        *reinterpret_cast<const __half2*>(h1b + (((unsigned)n << 7) + lo)));

    int j = beg;
    int head = (4 - (j & 3)) & 3;
    if (head > end - j) head = end - j;
    for (int q = 0; q < head; q++, j++) {
        unsigned off = (unsigned)__ldg(&g_csr[j]) + lo;
        float2 f = __half22float2(*reinterpret_cast<const __half2*>(h1b + off));
        acc.x += f.x; acc.y += f.y;
    }
    for (; j + 8 <= end; j += 8) {
        int4 a4 = __ldg(reinterpret_cast<const int4*>(&g_csr[j]));
        int4 b4 = __ldg(reinterpret_cast<const int4*>(&g_csr[j + 4]));
        __half2 v0 = *reinterpret_cast<const __half2*>(h1b + ((unsigned)a4.x + lo));
        __half2 v1 = *reinterpret_cast<const __half2*>(h1b + ((unsigned)a4.y + lo));
        __half2 v2 = *reinterpret_cast<const __half2*>(h1b + ((unsigned)a4.z + lo));
        __half2 v3 = *reinterpret_cast<const __half2*>(h1b + ((unsigned)a4.w + lo));
        __half2 v4 = *reinterpret_cast<const __half2*>(h1b + ((unsigned)b4.x + lo));
        __half2 v5 = *reinterpret_cast<const __half2*>(h1b + ((unsigned)b4.y + lo));
        __half2 v6 = *reinterpret_cast<const __half2*>(h1b + ((unsigned)b4.z + lo));
        __half2 v7 = *reinterpret_cast<const __half2*>(h1b + ((unsigned)b4.w + lo));
        float2 f0 = __half22float2(__hadd2(v0, v1));
        float2 f1 = __half22float2(__hadd2(v2, v3));
        float2 f2 = __half22float2(__hadd2(v4, v5));
        float2 f3 = __half22float2(__hadd2(v6, v7));
        acc.x += (f0.x + f1.x) + (f2.x + f3.x);
        acc.y += (f0.y + f1.y) + (f2.y + f3.y);
    }
    for (; j + 4 <= end; j += 4) {
        int4 a4 = __ldg(reinterpret_cast<const int4*>(&g_csr[j]));
        __half2 v0 = *reinterpret_cast<const __half2*>(h1b + ((unsigned)a4.x + lo));
        __half2 v1 = *reinterpret_cast<const __half2*>(h1b + ((unsigned)a4.y + lo));
        __half2 v2 = *reinterpret_cast<const __half2*>(h1b + ((unsigned)a4.z + lo));
        __half2 v3 = *reinterpret_cast<const __half2*>(h1b + ((unsigned)a4.w + lo));
        float2 f0 = __half22float2(__hadd2(v0, v1));
        float2 f1 = __half22float2(__hadd2(v2, v3));
        acc.x += f0.x + f1.x;
        acc.y += f0.y + f1.y;
    }
    for (; j < end; j++) {
        unsigned off = (unsigned)__ldg(&g_csr[j]) + lo;
        float2 f = __half22float2(*reinterpret_cast<const __half2*>(h1b + off));
        acc.x += f.x; acc.y += f.y;
    }

    *reinterpret_cast<float2*>(&g_agg1[(size_t)n * HID_F + lane * 2]) =
        make_float2(acc.x * dn, acc.y * dn);
}

// GEMM2: h2s = dis[n] * (relu(agg1 + b1) @ W2), fp16 out. 2 nodes/thread.
__global__ __launch_bounds__(256) void gemm2_kernel(
    const float* __restrict__ W2, const float* __restrict__ b1, int N) {
    __shared__ float Wsh[HID_F][OUT_F];
    __shared__ float bsh[HID_F];
    for (int i = threadIdx.x; i < HID_F * OUT_F; i += blockDim.x)
        Wsh[i >> 4][i & 15] = W2[i];
    if (threadIdx.x < HID_F) bsh[threadIdx.x] = b1[threadIdx.x];
    __syncthreads();

    int t = blockIdx.x * blockDim.x + threadIdx.x;
    int n0 = t * 2, n1 = t * 2 + 1;
    if (n0 >= N) return;
    bool has1 = (n1 < N);

    float acc0[OUT_F], acc1[OUT_F];
#pragma unroll
    for (int j = 0; j < OUT_F; j++) { acc0[j] = 0.0f; acc1[j] = 0.0f; }

    const float4* a0 = reinterpret_cast<const float4*>(&g_agg1[(size_t)n0 * HID_F]);
    const float4* a1 = reinterpret_cast<const float4*>(&g_agg1[(size_t)n1 * HID_F]);

#pragma unroll 4
    for (int k4 = 0; k4 < HID_F / 4; k4++) {
        float4 v0 = a0[k4];
        float4 v1 = has1 ? a1[k4] : make_float4(0.f, 0.f, 0.f, 0.f);
        float h0s[4] = {v0.x, v0.y, v0.z, v0.w};
        float h1s[4] = {v1.x, v1.y, v1.z, v1.w};
#pragma unroll
        for (int kk = 0; kk < 4; kk++) {
            int k = k4 * 4 + kk;
            float bb = bsh[k];
            float h0 = fmaxf(h0s[kk] + bb, 0.0f);
            float h1 = fmaxf(h1s[kk] + bb, 0.0f);
#pragma unroll
            for (int j4 = 0; j4 < OUT_F / 4; j4++) {
                float4 w = *reinterpret_cast<const float4*>(&Wsh[k][j4 * 4]);
                acc0[j4 * 4 + 0] += h0 * w.x;  acc1[j4 * 4 + 0] += h1 * w.x;
                acc0[j4 * 4 + 1] += h0 * w.y;  acc1[j4 * 4 + 1] += h1 * w.y;
                acc0[j4 * 4 + 2] += h0 * w.z;  acc1[j4 * 4 + 2] += h1 * w.z;
                acc0[j4 * 4 + 3] += h0 * w.w;  acc1[j4 * 4 + 3] += h1 * w.w;
            }
        }
    }

    {
        float d0 = g_dis[n0];
        __align__(16) __half2 h[8];
#pragma unroll
        for (int p = 0; p < 8; p++)
            h[p] = __floats2half2_rn(acc0[p * 2] * d0, acc0[p * 2 + 1] * d0);
        *reinterpret_cast<uint4*>(&g_h2[(size_t)n0 * OUT_F]) =
            *reinterpret_cast<uint4*>(&h[0]);
        *reinterpret_cast<uint4*>(&g_h2[(size_t)n0 * OUT_F + 8]) =
            *reinterpret_cast<uint4*>(&h[4]);
    }
    if (has1) {
        float d1 = g_dis[n1];
        __align__(16) __half2 h[8];
#pragma unroll
        for (int p = 0; p < 8; p++)
            h[p] = __floats2half2_rn(acc1[p * 2] * d1, acc1[p * 2 + 1] * d1);
        *reinterpret_cast<uint4*>(&g_h2[(size_t)n1 * OUT_F]) =
            *reinterpret_cast<uint4*>(&h[0]);
        *reinterpret_cast<uint4*>(&g_h2[(size_t)n1 * OUT_F + 8]) =
            *reinterpret_cast<uint4*>(&h[4]);
    }
}

// gather layer 2 + log_softmax — 8 lanes/node; h2 row offset = csr>>2.
// Resets g_cnt for next replay.
__global__ __launch_bounds__(256) void gather2_lsm_kernel(
    const float* __restrict__ b2, float* __restrict__ out, int N) {
    int t = blockIdx.x * blockDim.x + threadIdx.x;
    int n = t >> 3;
    int c = t & 7;
    if (n >= N) return;

    unsigned lane = threadIdx.x & 31;
    unsigned gmask = 0xffu << (lane & ~7u);

    const char* h2b = reinterpret_cast<const char*>(g_h2);
    unsigned lo = (unsigned)c * 4u;

    float dn = g_dis[n];
    int beg = g_row[n];
    int end = beg + g_cnt[n];

    float2 acc = __half22float2(
        *reinterpret_cast<const __half2*>(h2b + (((unsigned)n << 5) + lo)));

    int j = beg;
    int head = (4 - (j & 3)) & 3;
    if (head > end - j) head = end - j;
    for (int q = 0; q < head; q++, j++) {
        unsigned off = ((unsigned)__ldg(&g_csr[j]) >> 2) + lo;
        float2 f = __half22float2(*reinterpret_cast<const __half2*>(h2b + off));
        acc.x += f.x; acc.y += f.y;
    }
    for (; j + 4 <= end; j += 4) {
        int4 o4 = __ldg(reinterpret_cast<const int4*>(&g_csr[j]));
        __half2 a = *reinterpret_cast<const __half2*>(h2b + (((unsigned)o4.x >> 2) + lo));
        __half2 b = *reinterpret_cast<const __half2*>(h2b + (((unsigned)o4.y >> 2) + lo));
        __half2 cc = *reinterpret_cast<const __half2*>(h2b + (((unsigned)o4.z >> 2) + lo));
        __half2 d = *reinterpret_cast<const __half2*>(h2b + (((unsigned)o4.w >> 2) + lo));
        float2 f0 = __half22float2(__hadd2(a, b));
        float2 f1 = __half22float2(__hadd2(cc, d));
        acc.x += f0.x + f1.x;
        acc.y += f0.y + f1.y;
    }
    for (; j < end; j++) {
        unsigned off = ((unsigned)__ldg(&g_csr[j]) >> 2) + lo;
        float2 f = __half22float2(*reinterpret_cast<const __half2*>(h2b + off));
        acc.x += f.x; acc.y += f.y;
    }

    float2 bb = *reinterpret_cast<const float2*>(&b2[c * 2]);
    float v0 = acc.x * dn + bb.x;
    float v1 = acc.y * dn + bb.y;

    float mx = fmaxf(v0, v1);
    mx = fmaxf(mx, __shfl_xor_sync(gmask, mx, 1, 8));
    mx = fmaxf(mx, __shfl_xor_sync(gmask, mx, 2, 8));
    mx = fmaxf(mx, __shfl_xor_sync(gmask, mx, 4, 8));
    float s = __expf(v0 - mx) + __expf(v1 - mx);
    s += __shfl_xor_sync(gmask, s, 1, 8);
    s += __shfl_xor_sync(gmask, s, 2, 8);
    s += __shfl_xor_sync(gmask, s, 4, 8);
    float ls = mx + logf(s);

    *reinterpret_cast<float2*>(&out[(size_t)n * OUT_F + c * 2]) =
        make_float2(v0 - ls, v1 - ls);

    if (c == 0) g_cnt[n] = 0;
}

// ---------------------------------------------------------------------------
extern "C" void kernel_launch(void* const* d_in, const int* in_sizes, int n_in,
                              void* d_out, int out_size) {
    const float* x    = (const float*)d_in[0];
    const int*   ei32 = (const int*)d_in[1];
    const float* W1   = (const float*)d_in[2];
    const float* b1   = (const float*)d_in[3];
    const float* W2   = (const float*)d_in[4];
    const float* b2   = (const float*)d_in[5];
    float* out = (float*)d_out;

    int N = in_sizes[0] / IN_F;
    int E = in_sizes[1] / 2;

    const int T = 256;
    int gE = (E + T - 1) / T;
    int gN = (N + T - 1) / T;
    int nScanBlks = (N + SCAN_B - 1) / SCAN_B;

    static cudaStream_t s_side = 0;
    static cudaEvent_t ev_fork = 0, ev_dis = 0, ev_join = 0;
    static int s_init = 0;
    if (!s_init) {
        s_init = 1;
        if (cudaStreamCreateWithFlags(&s_side, cudaStreamNonBlocking) != cudaSuccess)
            s_side = 0;
        if (s_side) {
            if (cudaEventCreateWithFlags(&ev_fork, cudaEventDisableTiming) != cudaSuccess ||
                cudaEventCreateWithFlags(&ev_dis, cudaEventDisableTiming) != cudaSuccess ||
                cudaEventCreateWithFlags(&ev_join, cudaEventDisableTiming) != cudaSuccess)
                s_side = 0;
        }
    }

    if (s_side) {
        cudaEventRecord(ev_fork, 0);
        cudaStreamWaitEvent(s_side, ev_fork, 0);

        build_hist_kernel<<<gE, T, 0, s_side>>>(ei32, E);             // 1 (side)
        scan1_kernel<<<nScanBlks, SCAN_B, 0, s_side>>>(N);            // 2 (side)
        scan3_kernel<<<gN, T, 0, s_side>>>(N, nScanBlks);             // 3 (side)
        cudaEventRecord(ev_dis, s_side);

        gemm1_kernel<<<(N + 127) / 128, 256>>>(x, W1, N);             // 4 (main) <- profiled

        fill_kernel<<<gE, T, 0, s_side>>>(ei32, E);                   // 5 (side)
        cudaEventRecord(ev_join, s_side);

        cudaStreamWaitEvent(0, ev_dis, 0);
        scale_h1_kernel<<<(N * 8 + T - 1) / T, T>>>(N);               // 6 (main, ∥ fill)

        cudaStreamWaitEvent(0, ev_join, 0);
    } else {
        build_hist_kernel<<<gE, T>>>(ei32, E);
        scan1_kernel<<<nScanBlks, SCAN_B>>>(N);
        scan3_kernel<<<gN, T>>>(N, nScanBlks);
        gemm1_kernel<<<(N + 127) / 128, 256>>>(x, W1, N);
        fill_kernel<<<gE, T>>>(ei32, E);
        scale_h1_kernel<<<(N * 8 + T - 1) / T, T>>>(N);
    }

    gather1_kernel<<<(N * 32 + T - 1) / T, T>>>(N);                   // 7
    gemm2_kernel<<<((N + 1) / 2 + T - 1) / T, T>>>(W2, b1, N);        // 8
    gather2_lsm_kernel<<<(N * 8 + T - 1) / T, T>>>(b2, out, N);       // 9
}

// round 17
// speedup vs baseline: 1.1250x; 1.1250x over previous
#include <cuda_runtime.h>
#include <cuda_fp16.h>
#include <mma.h>
#include <math.h>
#include <stdint.h>

using namespace nvcuda;

#define N_NODES 100000
#define N_EDGES 1600000
#define IN_F 64
#define HID_F 64
#define OUT_F 16

#define SCAN_B 1024
#define MAX_SCAN_BLKS 128
#define XLD 72   // padded smem leading dim (halves); 144B = multiple of 16B

// ---- scratch (static __device__ globals) ----
__device__ __align__(16) int    g_cnt[N_NODES];
__device__ __align__(16) int    g_row[N_NODES];
__device__ __align__(16) int    g_rank[N_EDGES];
__device__ __align__(16) int    g_blksum[MAX_SCAN_BLKS];
__device__ __align__(16) float  g_dis[N_NODES];
__device__ __align__(16) int    g_csr[N_EDGES];     // src << 7 (byte offset of h1 row)
__device__ __align__(16) __half g_h1[(size_t)N_NODES * HID_F];        // dis*h1, fp16
// padded +128 rows: wmma stores full 16x16 tiles on the last block
__device__ __align__(16) float  g_agg1[(size_t)(N_NODES + 128) * HID_F];
__device__ __align__(16) __half g_h2[(size_t)N_NODES * OUT_F];        // dis*h2, fp16

// inline dtype detect: int64 node ids < 2^31 have zero odd 32-bit words
__device__ __forceinline__ int edge_stride(const int* __restrict__ ei32, int E) {
    int is64 = 1;
    int n = E < 16 ? E : 16;
#pragma unroll
    for (int i = 0; i < 16; i++)
        if (i < n && ei32[2 * i + 1] != 0) is64 = 0;
    return is64 ? 2 : 1;
}

// ---------------------------------------------------------------------------
// degree histogram on dst; stores per-edge rank within its bucket
__global__ void build_hist_kernel(const int* __restrict__ ei32, int E) {
    int e = blockIdx.x * blockDim.x + threadIdx.x;
    if (e >= E) return;
    int stride = edge_stride(ei32, E);
    int dst = ei32[((size_t)E + e) * stride];
    g_rank[e] = atomicAdd(&g_cnt[dst], 1);
}

// per-block exclusive scan (warp-shuffle, 2 barriers)
__global__ __launch_bounds__(SCAN_B) void scan1_kernel(int N) {
    __shared__ int wsum[32];
    int i = blockIdx.x * SCAN_B + threadIdx.x;
    int v = (i < N) ? g_cnt[i] : 0;
    int lane = threadIdx.x & 31, wid = threadIdx.x >> 5;

    int s = v;
#pragma unroll
    for (int o = 1; o < 32; o *= 2) {
        int t = __shfl_up_sync(0xffffffffu, s, o);
        if (lane >= o) s += t;
    }
    if (lane == 31) wsum[wid] = s;
    __syncthreads();
    if (wid == 0) {
        int w = wsum[lane];
        int ws = w;
#pragma unroll
        for (int o = 1; o < 32; o *= 2) {
            int t = __shfl_up_sync(0xffffffffu, ws, o);
            if (lane >= o) ws += t;
        }
        wsum[lane] = ws - w;
        if (lane == 31) g_blksum[blockIdx.x] = ws;
    }
    __syncthreads();
    if (i < N) g_row[i] = wsum[wid] + s - v;       // exclusive
}

// fixup: warp 0 scans block sums (4/lane); final offsets + dis
__global__ void scan3_kernel(int N, int nblks) {
    __shared__ int excl[MAX_SCAN_BLKS];
    int lane = threadIdx.x & 31;
    if (threadIdx.x < 32) {
        int b4 = lane * 4;
        int v0 = (b4 + 0 < nblks) ? g_blksum[b4 + 0] : 0;
        int v1 = (b4 + 1 < nblks) ? g_blksum[b4 + 1] : 0;
        int v2 = (b4 + 2 < nblks) ? g_blksum[b4 + 2] : 0;
        int v3 = (b4 + 3 < nblks) ? g_blksum[b4 + 3] : 0;
        int s4 = v0 + v1 + v2 + v3;
        int ss = s4;
#pragma unroll
        for (int o = 1; o < 32; o *= 2) {
            int t = __shfl_up_sync(0xffffffffu, ss, o);
            if (lane >= o) ss += t;
        }
        int ex = ss - s4;
        excl[b4 + 0] = ex;
        excl[b4 + 1] = ex + v0;
        excl[b4 + 2] = ex + v0 + v1;
        excl[b4 + 3] = ex + v0 + v1 + v2;
    }
    __syncthreads();
    int i = blockIdx.x * blockDim.x + threadIdx.x;
    if (i >= N) return;
    g_row[i] += excl[i >> 10];
    g_dis[i] = rsqrtf((float)(g_cnt[i] + 1));
}

// bucket fill — atomic-free; stores BYTE OFFSET of src's h1 row (src<<7)
__global__ void fill_kernel(const int* __restrict__ ei32, int E) {
    int e = blockIdx.x * blockDim.x + threadIdx.x;
    if (e >= E) return;
    int stride = edge_stride(ei32, E);
    int src = ei32[(size_t)e * stride];
    int dst = ei32[((size_t)E + e) * stride];
    g_csr[g_row[dst] + g_rank[e]] = src << 7;
}

// ---------------------------------------------------------------------------
// GEMM1 — tensor cores (wmma m16n16k16, fp16 in / fp32 acc):
//   g_agg1[n] = x[n] @ W1   (fp32, unscaled). 128-node tile, 8 warps.
__global__ __launch_bounds__(256) void gemm1_kernel(
    const float* __restrict__ x, const float* __restrict__ W1, int N) {
    __shared__ __half xh[128][XLD];   // 18KB
    __shared__ __half wh[IN_F][XLD];  // 9KB

    int tid = threadIdx.x;
    int nb = blockIdx.x * 128;

    // W1 fp32 -> half
    for (int i = tid; i < IN_F * HID_F / 4; i += 256) {
        int r = i >> 4, c4 = (i & 15) << 2;
        float4 v = *reinterpret_cast<const float4*>(&W1[r * HID_F + c4]);
        wh[r][c4 + 0] = __float2half(v.x);
        wh[r][c4 + 1] = __float2half(v.y);
        wh[r][c4 + 2] = __float2half(v.z);
        wh[r][c4 + 3] = __float2half(v.w);
    }
    // x tile fp32 -> half (zero-pad rows >= N)
    for (int i = tid; i < 128 * IN_F / 4; i += 256) {
        int r = i >> 4, c4 = (i & 15) << 2;
        int n = nb + r;
        float4 v = make_float4(0.f, 0.f, 0.f, 0.f);
        if (n < N)
            v = *reinterpret_cast<const float4*>(&x[(size_t)n * IN_F + c4]);
        xh[r][c4 + 0] = __float2half(v.x);
        xh[r][c4 + 1] = __float2half(v.y);
        xh[r][c4 + 2] = __float2half(v.z);
        xh[r][c4 + 3] = __float2half(v.w);
    }
    __syncthreads();

    int w = tid >> 5;   // warp id: rows w*16 .. w*16+15

    wmma::fragment<wmma::matrix_a, 16, 16, 16, __half, wmma::row_major> a[4];
#pragma unroll
    for (int k = 0; k < 4; k++)
        wmma::load_matrix_sync(a[k], &xh[w * 16][k * 16], XLD);

#pragma unroll
    for (int col = 0; col < 4; col++) {
        wmma::fragment<wmma::accumulator, 16, 16, 16, float> acc;
        wmma::fill_fragment(acc, 0.0f);
#pragma unroll
        for (int k = 0; k < 4; k++) {
            wmma::fragment<wmma::matrix_b, 16, 16, 16, __half, wmma::row_major> b;
            wmma::load_matrix_sync(b, &wh[k * 16][col * 16], XLD);
            wmma::mma_sync(acc, a[k], b, acc);
        }
        // g_agg1 is padded by 128 rows; full-tile store is safe on last block
        wmma::store_matrix_sync(
            &g_agg1[(size_t)(nb + w * 16) * HID_F + col * 16], acc,
            HID_F, wmma::mem_row_major);
    }
}

// convert + scale: g_h1[n] = half( g_agg1[n] * dis[n] ). 8 thr/node.
__global__ __launch_bounds__(256) void scale_h1_kernel(int N) {
    int t = blockIdx.x * blockDim.x + threadIdx.x;
    int n = t >> 3;
    int c = t & 7;
    if (n >= N) return;
    float dn = g_dis[n];
    const float4* src = reinterpret_cast<const float4*>(&g_agg1[(size_t)n * HID_F + c * 8]);
    float4 v0 = src[0];
    float4 v1 = src[1];
    __align__(16) __half2 h[4];
    h[0] = __floats2half2_rn(v0.x * dn, v0.y * dn);
    h[1] = __floats2half2_rn(v0.z * dn, v0.w * dn);
    h[2] = __floats2half2_rn(v1.x * dn, v1.y * dn);
    h[3] = __floats2half2_rn(v1.z * dn, v1.w * dn);
    *reinterpret_cast<uint4*>(&g_h1[(size_t)n * HID_F + c * 8]) =
        *reinterpret_cast<uint4*>(h);
}

// ---------------------------------------------------------------------------
// gather layer 1 — warp per node, offset csr, 8 edges/iter, 1 HADD2 level:
//   agg1[n] = dis[n] * ( h1s[n] + sum_s h1s[s] )    (fp32, into g_agg1)
__global__ __launch_bounds__(256) void gather1_kernel(int N) {
    int n = (blockIdx.x * blockDim.x + threadIdx.x) >> 5;
    unsigned lane = threadIdx.x & 31;
    if (n >= N) return;

    const char* h1b = reinterpret_cast<const char*>(g_h1);
    unsigned lo = lane * 4u;

    float dn = g_dis[n];
    int beg = g_row[n];
    int end = beg + g_cnt[n];

    float2 acc = __half22float2(
        *reinterpret_cast<const __half2*>(h1b + (((unsigned)n << 7) + lo)));

    int j = beg;
    int head = (4 - (j & 3)) & 3;
    if (head > end - j) head = end - j;
    for (int q = 0; q < head; q++, j++) {
        unsigned off = (unsigned)__ldg(&g_csr[j]) + lo;
        float2 f = __half22float2(*reinterpret_cast<const __half2*>(h1b + off));
        acc.x += f.x; acc.y += f.y;
    }
    for (; j + 8 <= end; j += 8) {
        int4 a4 = __ldg(reinterpret_cast<const int4*>(&g_csr[j]));
        int4 b4 = __ldg(reinterpret_cast<const int4*>(&g_csr[j + 4]));
        __half2 v0 = *reinterpret_cast<const __half2*>(h1b + ((unsigned)a4.x + lo));
        __half2 v1 = *reinterpret_cast<const __half2*>(h1b + ((unsigned)a4.y + lo));
        __half2 v2 = *reinterpret_cast<const __half2*>(h1b + ((unsigned)a4.z + lo));
        __half2 v3 = *reinterpret_cast<const __half2*>(h1b + ((unsigned)a4.w + lo));
        __half2 v4 = *reinterpret_cast<const __half2*>(h1b + ((unsigned)b4.x + lo));
        __half2 v5 = *reinterpret_cast<const __half2*>(h1b + ((unsigned)b4.y + lo));
        __half2 v6 = *reinterpret_cast<const __half2*>(h1b + ((unsigned)b4.z + lo));
        __half2 v7 = *reinterpret_cast<const __half2*>(h1b + ((unsigned)b4.w + lo));
        float2 f0 = __half22float2(__hadd2(v0, v1));
        float2 f1 = __half22float2(__hadd2(v2, v3));
        float2 f2 = __half22float2(__hadd2(v4, v5));
        float2 f3 = __half22float2(__hadd2(v6, v7));
        acc.x += (f0.x + f1.x) + (f2.x + f3.x);
        acc.y += (f0.y + f1.y) + (f2.y + f3.y);
    }
    for (; j + 4 <= end; j += 4) {
        int4 a4 = __ldg(reinterpret_cast<const int4*>(&g_csr[j]));
        __half2 v0 = *reinterpret_cast<const __half2*>(h1b + ((unsigned)a4.x + lo));
        __half2 v1 = *reinterpret_cast<const __half2*>(h1b + ((unsigned)a4.y + lo));
        __half2 v2 = *reinterpret_cast<const __half2*>(h1b + ((unsigned)a4.z + lo));
        __half2 v3 = *reinterpret_cast<const __half2*>(h1b + ((unsigned)a4.w + lo));
        float2 f0 = __half22float2(__hadd2(v0, v1));
        float2 f1 = __half22float2(__hadd2(v2, v3));
        acc.x += f0.x + f1.x;
        acc.y += f0.y + f1.y;
    }
    for (; j < end; j++) {
        unsigned off = (unsigned)__ldg(&g_csr[j]) + lo;
        float2 f = __half22float2(*reinterpret_cast<const __half2*>(h1b + off));
        acc.x += f.x; acc.y += f.y;
    }

    *reinterpret_cast<float2*>(&g_agg1[(size_t)n * HID_F + lane * 2]) =
        make_float2(acc.x * dn, acc.y * dn);
}

// GEMM2: h2s = dis[n] * (relu(agg1 + b1) @ W2), fp16 out. 2 nodes/thread.
__global__ __launch_bounds__(256) void gemm2_kernel(
    const float* __restrict__ W2, const float* __restrict__ b1, int N) {
    __shared__ float Wsh[HID_F][OUT_F];
    __shared__ float bsh[HID_F];
    for (int i = threadIdx.x; i < HID_F * OUT_F; i += blockDim.x)
        Wsh[i >> 4][i & 15] = W2[i];
    if (threadIdx.x < HID_F) bsh[threadIdx.x] = b1[threadIdx.x];
    __syncthreads();

    int t = blockIdx.x * blockDim.x + threadIdx.x;
    int n0 = t * 2, n1 = t * 2 + 1;
    if (n0 >= N) return;
    bool has1 = (n1 < N);

    float acc0[OUT_F], acc1[OUT_F];
#pragma unroll
    for (int j = 0; j < OUT_F; j++) { acc0[j] = 0.0f; acc1[j] = 0.0f; }

    const float4* a0 = reinterpret_cast<const float4*>(&g_agg1[(size_t)n0 * HID_F]);
    const float4* a1 = reinterpret_cast<const float4*>(&g_agg1[(size_t)n1 * HID_F]);

#pragma unroll 4
    for (int k4 = 0; k4 < HID_F / 4; k4++) {
        float4 v0 = a0[k4];
        float4 v1 = has1 ? a1[k4] : make_float4(0.f, 0.f, 0.f, 0.f);
        float h0s[4] = {v0.x, v0.y, v0.z, v0.w};
        float h1s[4] = {v1.x, v1.y, v1.z, v1.w};
#pragma unroll
        for (int kk = 0; kk < 4; kk++) {
            int k = k4 * 4 + kk;
            float bb = bsh[k];
            float h0 = fmaxf(h0s[kk] + bb, 0.0f);
            float h1 = fmaxf(h1s[kk] + bb, 0.0f);
#pragma unroll
            for (int j4 = 0; j4 < OUT_F / 4; j4++) {
                float4 w = *reinterpret_cast<const float4*>(&Wsh[k][j4 * 4]);
                acc0[j4 * 4 + 0] += h0 * w.x;  acc1[j4 * 4 + 0] += h1 * w.x;
                acc0[j4 * 4 + 1] += h0 * w.y;  acc1[j4 * 4 + 1] += h1 * w.y;
                acc0[j4 * 4 + 2] += h0 * w.z;  acc1[j4 * 4 + 2] += h1 * w.z;
                acc0[j4 * 4 + 3] += h0 * w.w;  acc1[j4 * 4 + 3] += h1 * w.w;
            }
        }
    }

    {
        float d0 = g_dis[n0];
        __align__(16) __half2 h[8];
#pragma unroll
        for (int p = 0; p < 8; p++)
            h[p] = __floats2half2_rn(acc0[p * 2] * d0, acc0[p * 2 + 1] * d0);
        *reinterpret_cast<uint4*>(&g_h2[(size_t)n0 * OUT_F]) =
            *reinterpret_cast<uint4*>(&h[0]);
        *reinterpret_cast<uint4*>(&g_h2[(size_t)n0 * OUT_F + 8]) =
            *reinterpret_cast<uint4*>(&h[4]);
    }
    if (has1) {
        float d1 = g_dis[n1];
        __align__(16) __half2 h[8];
#pragma unroll
        for (int p = 0; p < 8; p++)
            h[p] = __floats2half2_rn(acc1[p * 2] * d1, acc1[p * 2 + 1] * d1);
        *reinterpret_cast<uint4*>(&g_h2[(size_t)n1 * OUT_F]) =
            *reinterpret_cast<uint4*>(&h[0]);
        *reinterpret_cast<uint4*>(&g_h2[(size_t)n1 * OUT_F + 8]) =
            *reinterpret_cast<uint4*>(&h[4]);
    }
}

// gather layer 2 + log_softmax — 8 lanes/node; h2 row offset = csr>>2.
// Resets g_cnt for next replay.
__global__ __launch_bounds__(256) void gather2_lsm_kernel(
    const float* __restrict__ b2, float* __restrict__ out, int N) {
    int t = blockIdx.x * blockDim.x + threadIdx.x;
    int n = t >> 3;
    int c = t & 7;
    if (n >= N) return;

    unsigned lane = threadIdx.x & 31;
    unsigned gmask = 0xffu << (lane & ~7u);

    const char* h2b = reinterpret_cast<const char*>(g_h2);
    unsigned lo = (unsigned)c * 4u;

    float dn = g_dis[n];
    int beg = g_row[n];
    int end = beg + g_cnt[n];

    float2 acc = __half22float2(
        *reinterpret_cast<const __half2*>(h2b + (((unsigned)n << 5) + lo)));

    int j = beg;
    int head = (4 - (j & 3)) & 3;
    if (head > end - j) head = end - j;
    for (int q = 0; q < head; q++, j++) {
        unsigned off = ((unsigned)__ldg(&g_csr[j]) >> 2) + lo;
        float2 f = __half22float2(*reinterpret_cast<const __half2*>(h2b + off));
        acc.x += f.x; acc.y += f.y;
    }
    for (; j + 4 <= end; j += 4) {
        int4 o4 = __ldg(reinterpret_cast<const int4*>(&g_csr[j]));
        __half2 a = *reinterpret_cast<const __half2*>(h2b + (((unsigned)o4.x >> 2) + lo));
        __half2 b = *reinterpret_cast<const __half2*>(h2b + (((unsigned)o4.y >> 2) + lo));
        __half2 cc = *reinterpret_cast<const __half2*>(h2b + (((unsigned)o4.z >> 2) + lo));
        __half2 d = *reinterpret_cast<const __half2*>(h2b + (((unsigned)o4.w >> 2) + lo));
        float2 f0 = __half22float2(__hadd2(a, b));
        float2 f1 = __half22float2(__hadd2(cc, d));
        acc.x += f0.x + f1.x;
        acc.y += f0.y + f1.y;
    }
    for (; j < end; j++) {
        unsigned off = ((unsigned)__ldg(&g_csr[j]) >> 2) + lo;
        float2 f = __half22float2(*reinterpret_cast<const __half2*>(h2b + off));
        acc.x += f.x; acc.y += f.y;
    }

    float2 bb = *reinterpret_cast<const float2*>(&b2[c * 2]);
    float v0 = acc.x * dn + bb.x;
    float v1 = acc.y * dn + bb.y;

    float mx = fmaxf(v0, v1);
    mx = fmaxf(mx, __shfl_xor_sync(gmask, mx, 1, 8));
    mx = fmaxf(mx, __shfl_xor_sync(gmask, mx, 2, 8));
    mx = fmaxf(mx, __shfl_xor_sync(gmask, mx, 4, 8));
    float s = __expf(v0 - mx) + __expf(v1 - mx);
    s += __shfl_xor_sync(gmask, s, 1, 8);
    s += __shfl_xor_sync(gmask, s, 2, 8);
    s += __shfl_xor_sync(gmask, s, 4, 8);
    float ls = mx + logf(s);

    *reinterpret_cast<float2*>(&out[(size_t)n * OUT_F + c * 2]) =
        make_float2(v0 - ls, v1 - ls);

    if (c == 0) g_cnt[n] = 0;
}

// ---------------------------------------------------------------------------
extern "C" void kernel_launch(void* const* d_in, const int* in_sizes, int n_in,
                              void* d_out, int out_size) {
    const float* x    = (const float*)d_in[0];
    const int*   ei32 = (const int*)d_in[1];
    const float* W1   = (const float*)d_in[2];
    const float* b1   = (const float*)d_in[3];
    const float* W2   = (const float*)d_in[4];
    const float* b2   = (const float*)d_in[5];
    float* out = (float*)d_out;

    int N = in_sizes[0] / IN_F;
    int E = in_sizes[1] / 2;

    const int T = 256;
    int gE = (E + T - 1) / T;
    int gN = (N + T - 1) / T;
    int nScanBlks = (N + SCAN_B - 1) / SCAN_B;

    static cudaStream_t s_side = 0;
    static cudaEvent_t ev_fork = 0, ev_dis = 0, ev_join = 0;
    static int s_init = 0;
    if (!s_init) {
        s_init = 1;
        if (cudaStreamCreateWithFlags(&s_side, cudaStreamNonBlocking) != cudaSuccess)
            s_side = 0;
        if (s_side) {
            if (cudaEventCreateWithFlags(&ev_fork, cudaEventDisableTiming) != cudaSuccess ||
                cudaEventCreateWithFlags(&ev_dis, cudaEventDisableTiming) != cudaSuccess ||
                cudaEventCreateWithFlags(&ev_join, cudaEventDisableTiming) != cudaSuccess)
                s_side = 0;
        }
    }

    if (s_side) {
        cudaEventRecord(ev_fork, 0);
        cudaStreamWaitEvent(s_side, ev_fork, 0);

        build_hist_kernel<<<gE, T, 0, s_side>>>(ei32, E);             // 1 (side)
        scan1_kernel<<<nScanBlks, SCAN_B, 0, s_side>>>(N);            // 2 (side)
        scan3_kernel<<<gN, T, 0, s_side>>>(N, nScanBlks);             // 3 (side)
        cudaEventRecord(ev_dis, s_side);

        gemm1_kernel<<<(N + 127) / 128, 256>>>(x, W1, N);             // 4 (main) <- profiled

        fill_kernel<<<gE, T, 0, s_side>>>(ei32, E);                   // 5 (side)
        cudaEventRecord(ev_join, s_side);

        cudaStreamWaitEvent(0, ev_dis, 0);
        scale_h1_kernel<<<(N * 8 + T - 1) / T, T>>>(N);               // 6 (main, ∥ fill)

        cudaStreamWaitEvent(0, ev_join, 0);
    } else {
        build_hist_kernel<<<gE, T>>>(ei32, E);
        scan1_kernel<<<nScanBlks, SCAN_B>>>(N);
        scan3_kernel<<<gN, T>>>(N, nScanBlks);
        gemm1_kernel<<<(N + 127) / 128, 256>>>(x, W1, N);
        fill_kernel<<<gE, T>>>(ei32, E);
        scale_h1_kernel<<<(N * 8 + T - 1) / T, T>>>(N);
    }

    gather1_kernel<<<(N * 32 + T - 1) / T, T>>>(N);                   // 7
    gemm2_kernel<<<((N + 1) / 2 + T - 1) / T, T>>>(W2, b1, N);        // 8
    gather2_lsm_kernel<<<(N * 8 + T - 1) / T, T>>>(b2, out, N);       // 9
}